// round 1
// baseline (speedup 1.0000x reference)
#include <cuda_runtime.h>
#include <math.h>

// ---------------------------------------------------------------------------
// Problem constants
// ---------------------------------------------------------------------------
constexpr int Bn  = 8;      // batch
constexpr int SEQ = 2048;   // sequence length
constexpr int DX  = 128;    // input feature dim
constexpr int D   = 512;    // model dim (d_k = d_v = H*HD)
constexpr int H   = 8;      // heads
constexpr int HD  = 64;     // head dim
constexpr int Mtot = Bn * SEQ;   // 16384 flattened rows

// ---------------------------------------------------------------------------
// Scratch (allocation-free: __device__ globals)
// ---------------------------------------------------------------------------
__device__ float g_H  [Mtot * D];   // MLP hidden (reused for x1 then x2)
__device__ float g_K  [Mtot * D];   // k = mlp(x1)
__device__ float g_Q  [Mtot * D];   // q = mlp(x2)
__device__ float g_QH [Mtot * D];   // qh  [b,m,(h,e)]
__device__ float g_KH [Mtot * D];   // kh
__device__ float g_VH [Mtot * D];   // vh
__device__ float g_O  [Mtot * D];   // attention output [b,m,(h,e)]
__device__ float g_WoT[D * D];      // Wo transposed to [K=(h,e), N=d]

// ---------------------------------------------------------------------------
// Generic SGEMM: C[M,N] = A[M,K] * B + (bias) (+relu)
//   BT=false : B stored [K,N] row-major
//   BT=true  : B stored [N,K] row-major (i.e. C = A * B^T)
// BM=BN=128, BK=8, 256 threads, 8x8 per-thread tile.
// Requires M%128==0, N%128==0, K%8==0 (true for all our shapes).
// ---------------------------------------------------------------------------
template<int BM, int BN, int BK, bool BT, bool BIAS, bool RELU>
__global__ __launch_bounds__(256)
void sgemm_kernel(const float* __restrict__ A, const float* __restrict__ B,
                  const float* __restrict__ bias, float* __restrict__ C,
                  int M, int N, int K)
{
    __shared__ float As[BK][BM];
    __shared__ float Bs[BK][BN];

    const int tid = threadIdx.x;
    const int m0 = blockIdx.y * BM;
    const int n0 = blockIdx.x * BN;
    const int tx = tid & 15;   // 16 col-threads
    const int ty = tid >> 4;   // 16 row-threads

    // A-tile load mapping: 128x8 = 256 float4
    const int arow = tid >> 1;
    const int acol = (tid & 1) * 4;
    // B normal: 8x128 = 256 float4
    const int brow = tid >> 5;
    const int bcol = (tid & 31) * 4;
    // B transposed: 128x8 = 256 float4
    const int nrow = tid >> 1;
    const int kcol = (tid & 1) * 4;

    float acc[8][8];
    #pragma unroll
    for (int i = 0; i < 8; i++)
        #pragma unroll
        for (int j = 0; j < 8; j++) acc[i][j] = 0.f;

    for (int k0 = 0; k0 < K; k0 += BK) {
        float4 va = *(const float4*)&A[(m0 + arow) * K + k0 + acol];
        float4 vb;
        if (BT) vb = *(const float4*)&B[(n0 + nrow) * K + k0 + kcol];
        else    vb = *(const float4*)&B[(k0 + brow) * N + n0 + bcol];

        __syncthreads();   // previous compute done reading smem
        As[acol + 0][arow] = va.x;
        As[acol + 1][arow] = va.y;
        As[acol + 2][arow] = va.z;
        As[acol + 3][arow] = va.w;
        if (BT) {
            Bs[kcol + 0][nrow] = vb.x;
            Bs[kcol + 1][nrow] = vb.y;
            Bs[kcol + 2][nrow] = vb.z;
            Bs[kcol + 3][nrow] = vb.w;
        } else {
            *(float4*)&Bs[brow][bcol] = vb;
        }
        __syncthreads();

        #pragma unroll
        for (int kk = 0; kk < BK; kk++) {
            float a[8], b[8];
            *(float4*)&a[0] = *(const float4*)&As[kk][ty * 8];
            *(float4*)&a[4] = *(const float4*)&As[kk][ty * 8 + 4];
            *(float4*)&b[0] = *(const float4*)&Bs[kk][tx * 8];
            *(float4*)&b[4] = *(const float4*)&Bs[kk][tx * 8 + 4];
            #pragma unroll
            for (int i = 0; i < 8; i++)
                #pragma unroll
                for (int j = 0; j < 8; j++)
                    acc[i][j] = fmaf(a[i], b[j], acc[i][j]);
        }
    }

    #pragma unroll
    for (int i = 0; i < 8; i++) {
        const int row = m0 + ty * 8 + i;
        #pragma unroll
        for (int j4 = 0; j4 < 8; j4 += 4) {
            float4 v;
            float* pv = &v.x;
            #pragma unroll
            for (int j = 0; j < 4; j++) {
                float x = acc[i][j4 + j];
                if (BIAS) x += bias[n0 + tx * 8 + j4 + j];
                if (RELU) x = fmaxf(x, 0.f);
                pv[j] = x;
            }
            *(float4*)&C[row * N + n0 + tx * 8 + j4] = v;
        }
    }
}

// ---------------------------------------------------------------------------
// Wo transpose: WoT[(h*64+e)*512 + dd] = Wo[h*512*64 + dd*64 + e]
// ---------------------------------------------------------------------------
__global__ void transpose_wo_kernel(const float* __restrict__ Wo,
                                    float* __restrict__ WoT)
{
    int t = blockIdx.x * 256 + threadIdx.x;   // 0 .. 262143
    int he = t >> 9;          // (h*64+e)
    int dd = t & 511;
    int h = he >> 6, e = he & 63;
    WoT[t] = Wo[h * (512 * 64) + dd * 64 + e];
}

// ---------------------------------------------------------------------------
// Flash attention: per (b,h), online-softmax over 64x64 KV tiles.
// Grid (SEQ/64, H, Bn), 128 threads, 64KB dynamic smem.
// QH/KH/VH layout: [b, m, h*64+e] contiguous.
// Thread layout: tx = tid&7 (8 col-groups of 8), ry = tid>>3 (16 row-groups
// of 4). shfl_xor over lanes {1,2,4} reduces across the 8 col-threads.
// ---------------------------------------------------------------------------
constexpr int FBM = 64;
constexpr int FBN = 64;

__global__ __launch_bounds__(128)
void flash_kernel(const float* __restrict__ QH, const float* __restrict__ KH,
                  const float* __restrict__ VH, float* __restrict__ O)
{
    extern __shared__ float sm[];
    float* Qs = sm;                 // [HD][FBM]  (transposed)
    float* Ks = Qs + HD * FBM;      // [HD][FBN]  (transposed)
    float* Vs = Ks + HD * FBN;      // [FBN][HD]  (natural)
    float* Ps = Vs + FBN * HD;      // [FBN][FBM] (transposed)

    const int tid = threadIdx.x;
    const int tx = tid & 7;
    const int ry = tid >> 3;
    const int mtile = blockIdx.x, h = blockIdx.y, b = blockIdx.z;

    const int baseQ  = (b * SEQ + mtile * FBM) * D + h * HD;
    const int baseKV = (b * SEQ) * D + h * HD;

    // Q tile -> Qs[e][m]
    #pragma unroll
    for (int c = 0; c < 8; c++) {
        int p = c * 128 + tid;          // float4 index, 1024 total
        int m = p >> 4, e4 = (p & 15) * 4;
        float4 v = *(const float4*)&QH[baseQ + m * D + e4];
        Qs[(e4 + 0) * FBM + m] = v.x;
        Qs[(e4 + 1) * FBM + m] = v.y;
        Qs[(e4 + 2) * FBM + m] = v.z;
        Qs[(e4 + 3) * FBM + m] = v.w;
    }

    float o[4][8];
    float mrow[4], lrow[4];
    #pragma unroll
    for (int r = 0; r < 4; r++) {
        mrow[r] = -1e30f; lrow[r] = 0.f;
        #pragma unroll
        for (int c = 0; c < 8; c++) o[r][c] = 0.f;
    }
    const float scale = 0.125f;   // 1/sqrt(64)

    for (int nt = 0; nt < SEQ; nt += FBN) {
        __syncthreads();   // previous iter's P@V done with Vs/Ps
        // K tile -> Ks[e][n], V tile -> Vs[j][c]
        #pragma unroll
        for (int c = 0; c < 8; c++) {
            int p = c * 128 + tid;
            int n = p >> 4, e4 = (p & 15) * 4;
            float4 vk = *(const float4*)&KH[baseKV + (nt + n) * D + e4];
            Ks[(e4 + 0) * FBN + n] = vk.x;
            Ks[(e4 + 1) * FBN + n] = vk.y;
            Ks[(e4 + 2) * FBN + n] = vk.z;
            Ks[(e4 + 3) * FBN + n] = vk.w;
            float4 vv = *(const float4*)&VH[baseKV + (nt + n) * D + e4];
            *(float4*)&Vs[n * HD + e4] = vv;
        }
        __syncthreads();

        // S = Q K^T (64x64), thread owns 4 rows x 8 cols
        float s[4][8];
        #pragma unroll
        for (int r = 0; r < 4; r++)
            #pragma unroll
            for (int c = 0; c < 8; c++) s[r][c] = 0.f;

        #pragma unroll
        for (int kk = 0; kk < HD; kk++) {
            float a[4], bb[8];
            *(float4*)&a[0]  = *(const float4*)&Qs[kk * FBM + ry * 4];
            *(float4*)&bb[0] = *(const float4*)&Ks[kk * FBN + tx * 8];
            *(float4*)&bb[4] = *(const float4*)&Ks[kk * FBN + tx * 8 + 4];
            #pragma unroll
            for (int r = 0; r < 4; r++)
                #pragma unroll
                for (int c = 0; c < 8; c++)
                    s[r][c] = fmaf(a[r], bb[c], s[r][c]);
        }

        // online softmax (per row; reduce across 8 col-lanes via shfl)
        #pragma unroll
        for (int r = 0; r < 4; r++) {
            float tmax = -1e30f;
            #pragma unroll
            for (int c = 0; c < 8; c++) {
                s[r][c] *= scale;
                tmax = fmaxf(tmax, s[r][c]);
            }
            #pragma unroll
            for (int off = 1; off < 8; off <<= 1)
                tmax = fmaxf(tmax, __shfl_xor_sync(0xffffffffu, tmax, off));
            float mn = fmaxf(mrow[r], tmax);
            float alpha = __expf(mrow[r] - mn);
            float psum = 0.f;
            #pragma unroll
            for (int c = 0; c < 8; c++) {
                float p = __expf(s[r][c] - mn);
                s[r][c] = p;
                psum += p;
            }
            #pragma unroll
            for (int off = 1; off < 8; off <<= 1)
                psum += __shfl_xor_sync(0xffffffffu, psum, off);
            lrow[r] = lrow[r] * alpha + psum;
            mrow[r] = mn;
            #pragma unroll
            for (int c = 0; c < 8; c++) o[r][c] *= alpha;
        }

        // write P transposed: Ps[j][m]
        #pragma unroll
        for (int c = 0; c < 8; c++) {
            float4 v = make_float4(s[0][c], s[1][c], s[2][c], s[3][c]);
            *(float4*)&Ps[(tx * 8 + c) * FBM + ry * 4] = v;
        }
        __syncthreads();

        // O += P @ V
        #pragma unroll
        for (int j = 0; j < FBN; j++) {
            float p4[4], v8[8];
            *(float4*)&p4[0] = *(const float4*)&Ps[j * FBM + ry * 4];
            *(float4*)&v8[0] = *(const float4*)&Vs[j * HD + tx * 8];
            *(float4*)&v8[4] = *(const float4*)&Vs[j * HD + tx * 8 + 4];
            #pragma unroll
            for (int r = 0; r < 4; r++)
                #pragma unroll
                for (int c = 0; c < 8; c++)
                    o[r][c] = fmaf(p4[r], v8[c], o[r][c]);
        }
    }

    // normalize and store
    #pragma unroll
    for (int r = 0; r < 4; r++) {
        float inv = 1.f / lrow[r];
        int row = baseQ + (ry * 4 + r) * D + tx * 8;
        float4 v0 = make_float4(o[r][0] * inv, o[r][1] * inv,
                                o[r][2] * inv, o[r][3] * inv);
        float4 v1 = make_float4(o[r][4] * inv, o[r][5] * inv,
                                o[r][6] * inv, o[r][7] * inv);
        *(float4*)&O[row]     = v0;
        *(float4*)&O[row + 4] = v1;
    }
}

// ---------------------------------------------------------------------------
// Launch
// ---------------------------------------------------------------------------
extern "C" void kernel_launch(void* const* d_in, const int* in_sizes, int n_in,
                              void* d_out, int out_size)
{
    (void)in_sizes; (void)n_in; (void)out_size;
    const float* x1 = (const float*)d_in[0];
    const float* x2 = (const float*)d_in[1];
    const float* r  = (const float*)d_in[2];
    const float* W1 = (const float*)d_in[3];
    const float* b1 = (const float*)d_in[4];
    const float* W2 = (const float*)d_in[5];
    const float* b2 = (const float*)d_in[6];
    const float* Wq = (const float*)d_in[7];
    const float* Wk = (const float*)d_in[8];
    const float* Wv = (const float*)d_in[9];
    const float* Wo = (const float*)d_in[10];
    float* out = (float*)d_out;

    float *pH, *pK, *pQ, *pQH, *pKH, *pVH, *pO, *pWoT;
    cudaGetSymbolAddress((void**)&pH,   g_H);
    cudaGetSymbolAddress((void**)&pK,   g_K);
    cudaGetSymbolAddress((void**)&pQ,   g_Q);
    cudaGetSymbolAddress((void**)&pQH,  g_QH);
    cudaGetSymbolAddress((void**)&pKH,  g_KH);
    cudaGetSymbolAddress((void**)&pVH,  g_VH);
    cudaGetSymbolAddress((void**)&pO,   g_O);
    cudaGetSymbolAddress((void**)&pWoT, g_WoT);

    const dim3 gemm_grid(D / 128, Mtot / 128);   // (4, 128)
    const dim3 gemm_blk(256);

    // MLP: k = mlp(x1), q = mlp(x2)
    sgemm_kernel<128,128,8,false,true,true ><<<gemm_grid, gemm_blk>>>(x1, W1, b1, pH, Mtot, D, DX);
    sgemm_kernel<128,128,8,false,true,false><<<gemm_grid, gemm_blk>>>(pH, W2, b2, pK, Mtot, D, D);
    sgemm_kernel<128,128,8,false,true,true ><<<gemm_grid, gemm_blk>>>(x2, W1, b1, pH, Mtot, D, DX);
    sgemm_kernel<128,128,8,false,true,false><<<gemm_grid, gemm_blk>>>(pH, W2, b2, pQ, Mtot, D, D);

    // Head projections: Wq/Wk/Wv are [H*hd, d] = [N, K] -> B-transposed path
    sgemm_kernel<128,128,8,true,false,false><<<gemm_grid, gemm_blk>>>(pQ, Wq, nullptr, pQH, Mtot, D, D);
    sgemm_kernel<128,128,8,true,false,false><<<gemm_grid, gemm_blk>>>(pK, Wk, nullptr, pKH, Mtot, D, D);
    sgemm_kernel<128,128,8,true,false,false><<<gemm_grid, gemm_blk>>>(r,  Wv, nullptr, pVH, Mtot, D, D);

    // Wo -> [K=(h,e), N=d]
    transpose_wo_kernel<<<(D * D) / 256, 256>>>(Wo, pWoT);

    // Flash attention
    cudaFuncSetAttribute(flash_kernel,
                         cudaFuncAttributeMaxDynamicSharedMemorySize, 65536);
    flash_kernel<<<dim3(SEQ / FBM, H, Bn), 128, 65536>>>(pQH, pKH, pVH, pO);

    // Output projection -> d_out
    sgemm_kernel<128,128,8,false,false,false><<<gemm_grid, gemm_blk>>>(pO, pWoT, nullptr, out, Mtot, D, D);
}

// round 8
// speedup vs baseline: 2.7732x; 2.7732x over previous
#include <cuda_runtime.h>
#include <math.h>

// ---------------------------------------------------------------------------
// Problem constants
// ---------------------------------------------------------------------------
constexpr int Bn  = 8;
constexpr int SEQ = 2048;
constexpr int DX  = 128;
constexpr int D   = 512;
constexpr int H   = 8;
constexpr int HD  = 64;
constexpr int Mtot = Bn * SEQ;   // 16384

// ---------------------------------------------------------------------------
// Scratch
// ---------------------------------------------------------------------------
__device__ float g_H  [Mtot * D];
__device__ float g_K  [Mtot * D];
__device__ float g_Q  [Mtot * D];
__device__ float g_QH [Mtot * D];
__device__ float g_KH [Mtot * D];
__device__ float g_VH [Mtot * D];
__device__ float g_O  [Mtot * D];
__device__ float g_WoT[D * D];

// ---------------------------------------------------------------------------
// tf32 helpers
// ---------------------------------------------------------------------------
__device__ __forceinline__ unsigned f2tf(float x) {
    unsigned r;
    asm("cvt.rna.tf32.f32 %0, %1;" : "=r"(r) : "f"(x));
    return r;
}

__device__ __forceinline__ void mma_tf32(float d[4], const unsigned a[4],
                                         const unsigned b[2]) {
    asm("mma.sync.aligned.m16n8k8.row.col.f32.tf32.tf32.f32 "
        "{%0,%1,%2,%3},{%4,%5,%6,%7},{%8,%9},{%0,%1,%2,%3};"
        : "+f"(d[0]), "+f"(d[1]), "+f"(d[2]), "+f"(d[3])
        : "r"(a[0]), "r"(a[1]), "r"(a[2]), "r"(a[3]),
          "r"(b[0]), "r"(b[1]));
}

// ---------------------------------------------------------------------------
// tf32 GEMM: C[M,N] = A[M,K] * B (+bias)(+relu)
//   BT=false: B is [K,N]; BT=true: B is [N,K] (C = A*B^T)
// 128x128x32 CTA tile, 256 threads (8 warps in 2x4), warp tile 64x32.
// Software-pipelined: gmem tile k+1 prefetched into registers during
// compute of tile k (numerics-neutral vs non-pipelined version).
// ---------------------------------------------------------------------------
constexpr int ASTR = 36;    // As row stride (floats) — conflict-free frag loads
constexpr int BSTR = 136;   // Bs row stride

template<bool BT, bool BIAS, bool RELU>
__global__ __launch_bounds__(256)
void mma_gemm_kernel(const float* __restrict__ A, const float* __restrict__ B,
                     const float* __restrict__ bias, float* __restrict__ C,
                     int M, int N, int K)
{
    __shared__ unsigned As[128 * ASTR];
    __shared__ unsigned Bs[32 * BSTR];

    const int tid  = threadIdx.x;
    const int lane = tid & 31;
    const int warp = tid >> 5;
    const int grp  = lane >> 2;   // 0..7
    const int qid  = lane & 3;    // 0..3
    const int wm   = warp >> 2;   // 0..1 -> row offset wm*64
    const int wn   = warp & 3;    // 0..3 -> col offset wn*32
    const int m0 = blockIdx.y * 128;
    const int n0 = blockIdx.x * 128;

    float acc[4][4][4];
    #pragma unroll
    for (int i = 0; i < 4; i++)
        #pragma unroll
        for (int j = 0; j < 4; j++)
            #pragma unroll
            for (int v = 0; v < 4; v++) acc[i][j][v] = 0.f;

    float4 va[4], vb[4];

    // ---- prologue: load tile k0 = 0 into registers ----
    #pragma unroll
    for (int i = 0; i < 4; i++) {
        int idx = tid + i * 256;          // 0..1023
        int row = idx >> 3, c4 = (idx & 7) * 4;
        va[i] = *(const float4*)&A[(m0 + row) * K + c4];
    }
    #pragma unroll
    for (int i = 0; i < 4; i++) {
        int idx = tid + i * 256;
        if (BT) {
            int n = idx >> 3, k4 = (idx & 7) * 4;
            vb[i] = *(const float4*)&B[(n0 + n) * K + k4];
        } else {
            int row = idx >> 5, c4 = (idx & 31) * 4;
            vb[i] = *(const float4*)&B[row * N + n0 + c4];
        }
    }

    for (int k0 = 0; k0 < K; k0 += 32) {
        __syncthreads();   // previous compute done reading smem
        // ---- store current tile (registers -> smem, with tf32 cvt) ----
        #pragma unroll
        for (int i = 0; i < 4; i++) {
            int idx = tid + i * 256;
            int row = idx >> 3, c4 = (idx & 7) * 4;
            uint4 u = make_uint4(f2tf(va[i].x), f2tf(va[i].y),
                                 f2tf(va[i].z), f2tf(va[i].w));
            *(uint4*)&As[row * ASTR + c4] = u;
        }
        #pragma unroll
        for (int i = 0; i < 4; i++) {
            int idx = tid + i * 256;
            if (BT) {
                int n = idx >> 3, k4 = (idx & 7) * 4;
                Bs[(k4 + 0) * BSTR + n] = f2tf(vb[i].x);
                Bs[(k4 + 1) * BSTR + n] = f2tf(vb[i].y);
                Bs[(k4 + 2) * BSTR + n] = f2tf(vb[i].z);
                Bs[(k4 + 3) * BSTR + n] = f2tf(vb[i].w);
            } else {
                int row = idx >> 5, c4 = (idx & 31) * 4;
                uint4 u = make_uint4(f2tf(vb[i].x), f2tf(vb[i].y),
                                     f2tf(vb[i].z), f2tf(vb[i].w));
                *(uint4*)&Bs[row * BSTR + c4] = u;
            }
        }
        __syncthreads();

        // ---- prefetch next tile into registers (overlaps with compute) ----
        const int kn = k0 + 32;
        if (kn < K) {
            #pragma unroll
            for (int i = 0; i < 4; i++) {
                int idx = tid + i * 256;
                int row = idx >> 3, c4 = (idx & 7) * 4;
                va[i] = *(const float4*)&A[(m0 + row) * K + kn + c4];
            }
            #pragma unroll
            for (int i = 0; i < 4; i++) {
                int idx = tid + i * 256;
                if (BT) {
                    int n = idx >> 3, k4 = (idx & 7) * 4;
                    vb[i] = *(const float4*)&B[(n0 + n) * K + kn + k4];
                } else {
                    int row = idx >> 5, c4 = (idx & 31) * 4;
                    vb[i] = *(const float4*)&B[(kn + row) * N + n0 + c4];
                }
            }
        }

        // ---- compute: 4 k-steps of 8 ----
        #pragma unroll
        for (int ks = 0; ks < 4; ks++) {
            const int k8 = ks * 8;
            unsigned af[4][4], bf[4][2];
            #pragma unroll
            for (int mt = 0; mt < 4; mt++) {
                int r = wm * 64 + mt * 16 + grp;
                int c = k8 + qid;
                af[mt][0] = As[r * ASTR + c];
                af[mt][1] = As[(r + 8) * ASTR + c];
                af[mt][2] = As[r * ASTR + c + 4];
                af[mt][3] = As[(r + 8) * ASTR + c + 4];
            }
            #pragma unroll
            for (int nt = 0; nt < 4; nt++) {
                int n = wn * 32 + nt * 8 + grp;
                bf[nt][0] = Bs[(k8 + qid) * BSTR + n];
                bf[nt][1] = Bs[(k8 + qid + 4) * BSTR + n];
            }
            #pragma unroll
            for (int mt = 0; mt < 4; mt++)
                #pragma unroll
                for (int nt = 0; nt < 4; nt++)
                    mma_tf32(acc[mt][nt], af[mt], bf[nt]);
        }
    }

    // ---- epilogue ----
    #pragma unroll
    for (int mt = 0; mt < 4; mt++) {
        #pragma unroll
        for (int nt = 0; nt < 4; nt++) {
            int r = m0 + wm * 64 + mt * 16 + grp;
            int c = n0 + wn * 32 + nt * 8 + 2 * qid;
            float v0 = acc[mt][nt][0], v1 = acc[mt][nt][1];
            float v2 = acc[mt][nt][2], v3 = acc[mt][nt][3];
            if (BIAS) {
                float bb0 = bias[c], bb1 = bias[c + 1];
                v0 += bb0; v1 += bb1; v2 += bb0; v3 += bb1;
            }
            if (RELU) {
                v0 = fmaxf(v0, 0.f); v1 = fmaxf(v1, 0.f);
                v2 = fmaxf(v2, 0.f); v3 = fmaxf(v3, 0.f);
            }
            *(float2*)&C[r * N + c]       = make_float2(v0, v1);
            *(float2*)&C[(r + 8) * N + c] = make_float2(v2, v3);
        }
    }
}

// ---------------------------------------------------------------------------
// Wo transpose
// ---------------------------------------------------------------------------
__global__ void transpose_wo_kernel(const float* __restrict__ Wo,
                                    float* __restrict__ WoT)
{
    int t = blockIdx.x * 256 + threadIdx.x;
    int he = t >> 9, dd = t & 511;
    int h = he >> 6, e = he & 63;
    WoT[t] = Wo[h * (512 * 64) + dd * 64 + e];
}

// ---------------------------------------------------------------------------
// Flash attention, tf32 MMA. Grid (32, H, Bn), 128 threads (4 warps).
// Warp w owns Q rows [w*16, w*16+16) and full 64 columns -> intra-warp softmax.
// Softmax in exp2 domain (log2e folded into Q scale).
// ---------------------------------------------------------------------------
constexpr int KSTR = 72;   // Ks/Vs row stride
constexpr int PSTR = 68;   // Qs/Ps row stride

__global__ __launch_bounds__(128)
void flash_mma_kernel(const float* __restrict__ QH, const float* __restrict__ KH,
                      const float* __restrict__ VH, float* __restrict__ O)
{
    extern __shared__ unsigned sm[];
    unsigned* Ks = sm;                  // [64 hd][72]  K^T
    unsigned* Vs = Ks + 64 * KSTR;      // [64 kv][72]  natural
    unsigned* Ps = Vs + 64 * KSTR;      // [64][68]  (also Q staging)

    const int tid  = threadIdx.x;
    const int lane = tid & 31;
    const int warp = tid >> 5;
    const int grp  = lane >> 2;
    const int qid  = lane & 3;
    const int mtile = blockIdx.x, h = blockIdx.y, b = blockIdx.z;

    const int baseQ  = (b * SEQ + mtile * 64) * D + h * HD;
    const int baseKV = (b * SEQ) * D + h * HD;
    const float softscale = 0.125f * 1.4426950408889634f;  // 1/sqrt(64)*log2e

    // ---- stage Q into Ps buffer (scaled + tf32), then hoist frags to regs ----
    #pragma unroll
    for (int i = 0; i < 8; i++) {
        int idx = tid + i * 128;          // 1024 float4
        int row = idx >> 4, c4 = (idx & 15) * 4;
        float4 v = *(const float4*)&QH[baseQ + row * D + c4];
        uint4 u = make_uint4(f2tf(v.x * softscale), f2tf(v.y * softscale),
                             f2tf(v.z * softscale), f2tf(v.w * softscale));
        *(uint4*)&Ps[row * PSTR + c4] = u;
    }
    __syncthreads();

    unsigned qf[8][4];   // 8 k-steps over hd=64
    {
        int r = warp * 16 + grp;
        #pragma unroll
        for (int ks = 0; ks < 8; ks++) {
            int c = ks * 8 + qid;
            qf[ks][0] = Ps[r * PSTR + c];
            qf[ks][1] = Ps[(r + 8) * PSTR + c];
            qf[ks][2] = Ps[r * PSTR + c + 4];
            qf[ks][3] = Ps[(r + 8) * PSTR + c + 4];
        }
    }

    float o[8][4];
    #pragma unroll
    for (int nt = 0; nt < 8; nt++)
        #pragma unroll
        for (int v = 0; v < 4; v++) o[nt][v] = 0.f;
    float m0 = -1e30f, m1 = -1e30f, l0 = 0.f, l1 = 0.f;

    for (int nt0 = 0; nt0 < SEQ; nt0 += 64) {
        __syncthreads();   // prev iter done reading Vs; Q-frag reads done
        // ---- load K (transposed) and V (natural), cvt tf32 ----
        #pragma unroll
        for (int i = 0; i < 8; i++) {
            int idx = tid + i * 128;
            int n = idx >> 4, e4 = (idx & 15) * 4;
            float4 vk = *(const float4*)&KH[baseKV + (nt0 + n) * D + e4];
            Ks[(e4 + 0) * KSTR + n] = f2tf(vk.x);
            Ks[(e4 + 1) * KSTR + n] = f2tf(vk.y);
            Ks[(e4 + 2) * KSTR + n] = f2tf(vk.z);
            Ks[(e4 + 3) * KSTR + n] = f2tf(vk.w);
            float4 vv = *(const float4*)&VH[baseKV + (nt0 + n) * D + e4];
            uint4 u = make_uint4(f2tf(vv.x), f2tf(vv.y), f2tf(vv.z), f2tf(vv.w));
            *(uint4*)&Vs[n * KSTR + e4] = u;
        }
        __syncthreads();

        // ---- S = (scale*log2e) * Q K^T ----
        float s[8][4];
        #pragma unroll
        for (int nt = 0; nt < 8; nt++)
            #pragma unroll
            for (int v = 0; v < 4; v++) s[nt][v] = 0.f;

        #pragma unroll
        for (int ks = 0; ks < 8; ks++) {
            const int k8 = ks * 8;
            #pragma unroll
            for (int nt = 0; nt < 8; nt++) {
                unsigned bf[2];
                bf[0] = Ks[(k8 + qid) * KSTR + nt * 8 + grp];
                bf[1] = Ks[(k8 + qid + 4) * KSTR + nt * 8 + grp];
                mma_tf32(s[nt], qf[ks], bf);
            }
        }

        // ---- online softmax (exp2 domain), rows grp and grp+8 ----
        float rmax0 = -1e30f, rmax1 = -1e30f;
        #pragma unroll
        for (int nt = 0; nt < 8; nt++) {
            rmax0 = fmaxf(rmax0, fmaxf(s[nt][0], s[nt][1]));
            rmax1 = fmaxf(rmax1, fmaxf(s[nt][2], s[nt][3]));
        }
        rmax0 = fmaxf(rmax0, __shfl_xor_sync(0xffffffffu, rmax0, 1));
        rmax0 = fmaxf(rmax0, __shfl_xor_sync(0xffffffffu, rmax0, 2));
        rmax1 = fmaxf(rmax1, __shfl_xor_sync(0xffffffffu, rmax1, 1));
        rmax1 = fmaxf(rmax1, __shfl_xor_sync(0xffffffffu, rmax1, 2));

        float mn0 = fmaxf(m0, rmax0), mn1 = fmaxf(m1, rmax1);
        float alpha0 = exp2f(m0 - mn0), alpha1 = exp2f(m1 - mn1);
        m0 = mn0; m1 = mn1;

        float rsum0 = 0.f, rsum1 = 0.f;
        const int r = warp * 16 + grp;
        #pragma unroll
        for (int nt = 0; nt < 8; nt++) {
            float p0 = exp2f(s[nt][0] - m0);
            float p1 = exp2f(s[nt][1] - m0);
            float p2 = exp2f(s[nt][2] - m1);
            float p3 = exp2f(s[nt][3] - m1);
            rsum0 += p0 + p1;
            rsum1 += p2 + p3;
            int c = nt * 8 + 2 * qid;
            *(uint2*)&Ps[r * PSTR + c]       = make_uint2(f2tf(p0), f2tf(p1));
            *(uint2*)&Ps[(r + 8) * PSTR + c] = make_uint2(f2tf(p2), f2tf(p3));
        }
        rsum0 += __shfl_xor_sync(0xffffffffu, rsum0, 1);
        rsum0 += __shfl_xor_sync(0xffffffffu, rsum0, 2);
        rsum1 += __shfl_xor_sync(0xffffffffu, rsum1, 1);
        rsum1 += __shfl_xor_sync(0xffffffffu, rsum1, 2);
        l0 = l0 * alpha0 + rsum0;
        l1 = l1 * alpha1 + rsum1;

        #pragma unroll
        for (int nt = 0; nt < 8; nt++) {
            o[nt][0] *= alpha0; o[nt][1] *= alpha0;
            o[nt][2] *= alpha1; o[nt][3] *= alpha1;
        }
        __syncwarp();   // Ps rows are warp-private: warp sync suffices

        // ---- O += P @ V ----
        #pragma unroll
        for (int ks = 0; ks < 8; ks++) {
            const int k8 = ks * 8;
            unsigned af[4];
            af[0] = Ps[r * PSTR + k8 + qid];
            af[1] = Ps[(r + 8) * PSTR + k8 + qid];
            af[2] = Ps[r * PSTR + k8 + qid + 4];
            af[3] = Ps[(r + 8) * PSTR + k8 + qid + 4];
            #pragma unroll
            for (int nt = 0; nt < 8; nt++) {
                unsigned bf[2];
                bf[0] = Vs[(k8 + qid) * KSTR + nt * 8 + grp];
                bf[1] = Vs[(k8 + qid + 4) * KSTR + nt * 8 + grp];
                mma_tf32(o[nt], af, bf);
            }
        }
    }

    // ---- normalize + store ----
    float inv0 = 1.f / l0, inv1 = 1.f / l1;
    const int row = mtile * 64 + warp * 16 + grp;
    #pragma unroll
    for (int nt = 0; nt < 8; nt++) {
        int c = h * HD + nt * 8 + 2 * qid;
        *(float2*)&O[(b * SEQ + row) * D + c] =
            make_float2(o[nt][0] * inv0, o[nt][1] * inv0);
        *(float2*)&O[(b * SEQ + row + 8) * D + c] =
            make_float2(o[nt][2] * inv1, o[nt][3] * inv1);
    }
}

// ---------------------------------------------------------------------------
// Launch
// ---------------------------------------------------------------------------
extern "C" void kernel_launch(void* const* d_in, const int* in_sizes, int n_in,
                              void* d_out, int out_size)
{
    (void)in_sizes; (void)n_in; (void)out_size;
    const float* x1 = (const float*)d_in[0];
    const float* x2 = (const float*)d_in[1];
    const float* r  = (const float*)d_in[2];
    const float* W1 = (const float*)d_in[3];
    const float* b1 = (const float*)d_in[4];
    const float* W2 = (const float*)d_in[5];
    const float* b2 = (const float*)d_in[6];
    const float* Wq = (const float*)d_in[7];
    const float* Wk = (const float*)d_in[8];
    const float* Wv = (const float*)d_in[9];
    const float* Wo = (const float*)d_in[10];
    float* out = (float*)d_out;

    float *pH, *pK, *pQ, *pQH, *pKH, *pVH, *pO, *pWoT;
    cudaGetSymbolAddress((void**)&pH,   g_H);
    cudaGetSymbolAddress((void**)&pK,   g_K);
    cudaGetSymbolAddress((void**)&pQ,   g_Q);
    cudaGetSymbolAddress((void**)&pQH,  g_QH);
    cudaGetSymbolAddress((void**)&pKH,  g_KH);
    cudaGetSymbolAddress((void**)&pVH,  g_VH);
    cudaGetSymbolAddress((void**)&pO,   g_O);
    cudaGetSymbolAddress((void**)&pWoT, g_WoT);

    const dim3 gg(D / 128, Mtot / 128);   // (4, 128)
    const dim3 gb(256);

    // MLP
    mma_gemm_kernel<false, true, true ><<<gg, gb>>>(x1, W1, b1, pH, Mtot, D, DX);
    mma_gemm_kernel<false, true, false><<<gg, gb>>>(pH, W2, b2, pK, Mtot, D, D);
    mma_gemm_kernel<false, true, true ><<<gg, gb>>>(x2, W1, b1, pH, Mtot, D, DX);
    mma_gemm_kernel<false, true, false><<<gg, gb>>>(pH, W2, b2, pQ, Mtot, D, D);

    // Head projections (B stored [N,K] -> BT path)
    mma_gemm_kernel<true, false, false><<<gg, gb>>>(pQ, Wq, nullptr, pQH, Mtot, D, D);
    mma_gemm_kernel<true, false, false><<<gg, gb>>>(pK, Wk, nullptr, pKH, Mtot, D, D);
    mma_gemm_kernel<true, false, false><<<gg, gb>>>(r,  Wv, nullptr, pVH, Mtot, D, D);

    transpose_wo_kernel<<<(D * D) / 256, 256>>>(Wo, pWoT);

    // Flash attention
    const int fsmem = (2 * 64 * KSTR + 64 * PSTR) * 4;   // 54272 B
    cudaFuncSetAttribute(flash_mma_kernel,
                         cudaFuncAttributeMaxDynamicSharedMemorySize, fsmem);
    flash_mma_kernel<<<dim3(SEQ / 64, H, Bn), 128, fsmem>>>(pQH, pKH, pVH, pO);

    // Output projection
    mma_gemm_kernel<false, false, false><<<gg, gb>>>(pO, pWoT, nullptr, out, Mtot, D, D);
}